// round 15
// baseline (speedup 1.0000x reference)
#include <cuda_runtime.h>
#include <cuda_bf16.h>
#include <math.h>

// Problem constants
#define T_STEPS 128
#define BATCH   64
#define NTOKEN  10000
#define NB      6
#define BS      100
#define NHID    600
#define EMHA    64
#define DEC_ELEMS 81920000L
#define HX_ELEMS  38400

#define N_RNN_CTAS 64
#define N_PAIRS    32
#define N_NTILES   79
#define N_MTILES   64

// -------------------- device scratch --------------------
__device__ float g_outputs[T_STEPS * BATCH * NHID];
__device__ float g_gruT_ih[NB * BS * 3 * BS];         // [k][d][g]
__device__ float g_gruT_hh[NB * BS * 3 * BS];
__device__ float g_mhafcT[EMHA * BS];                 // [e][i]
__device__ float g_gateT[EMHA * BS];
__device__ int   g_flag[T_STEPS];                     // per-step rnn completion (0..64)
__device__ int   g_sync[N_PAIRS][2];                  // per-CTA monotonic release counter
__device__ float g_xA[2][N_PAIRS][2][256];            // parity: k0/v0 halves [kv][bb][64]
__device__ float g_xB[2][N_PAIRS][2][8];              // a0 own 3 scores [bb][4]
__device__ float g_xC[2][N_PAIRS][2][1152];           // qkv own blocks [bb][576]

// -------------------- prep: transposes + counter reset --------------------
__global__ void prep_kernel(const float* __restrict__ w_ih, const float* __restrict__ w_hh,
                            const float* __restrict__ mfc, const float* __restrict__ mgate) {
    int i = blockIdx.x * blockDim.x + threadIdx.x;
    if (i < T_STEPS) g_flag[i] = 0;
    if (i < N_PAIRS * 2) ((int*)g_sync)[i] = 0;
    if (i < NB * 3 * BS * BS) {
        int k = i / (3 * BS * BS);
        int r = i % (3 * BS * BS);
        int g = r / BS;
        int d = r % BS;
        int dst = k * (BS * 3 * BS) + d * (3 * BS) + g;
        g_gruT_ih[dst] = w_ih[i];
        g_gruT_hh[dst] = w_hh[i];
    }
    if (i < BS * EMHA) {
        int r = i / EMHA;
        int e = i % EMHA;
        g_mhafcT[e * BS + r] = mfc[i];
        g_gateT[e * BS + r]  = mgate[i];
    }
}

// -------------------- helpers --------------------
__device__ __forceinline__ float sigmoidf_(float x) { return 1.f / (1.f + expf(-x)); }
__device__ __forceinline__ void ffma2(unsigned long long& a, unsigned long long x, unsigned long long y) {
    asm("fma.rn.f32x2 %0, %1, %2, %0;" : "+l"(a) : "l"(x), "l"(y));
}
__device__ __forceinline__ unsigned long long bc2(float x) {
    unsigned long long r;
    asm("mov.b64 %0, {%1, %1};" : "=l"(r) : "r"(__float_as_uint(x)));
    return r;
}
__device__ __forceinline__ float2 up2(unsigned long long a) {
    unsigned lo, hi;
    asm("mov.b64 {%0, %1}, %2;" : "=r"(lo), "=r"(hi) : "l"(a));
    return make_float2(__uint_as_float(lo), __uint_as_float(hi));
}

// -------------------- rnn smem layout (floats) --------------------
#define OFF_HX    0        // [2][300] own blocks
#define OFF_X     600      // [2][600]
#define OFF_IU    1800     // [2][300]
#define OFF_HN    2400     // [2][300]
#define OFF_GX    3000     // [2][900]
#define OFF_GH    4800     // [2][900]
#define OFF_RED   6600     // [16][2][64] k0/v0 partials
#define OFF_REDQ  8648     // [6][2][128] qp partials
#define OFF_K0    10184    // [2][128] full
#define OFF_V0    10440    // [2][128] full
#define OFF_QP    10696    // [2][384] own
#define OFF_P     11464    // [2][104]
#define OFF_A0    11672    // [2][8] full
#define OFF_MASK  11688    // [2][8]
#define OFF_QKVP  11704    // [2dp][2bb][576]
#define OFF_QKVF  14008    // [2][1152] full (q|k|v x n6 x 64)
#define OFF_AW    16312    // [2][144]
#define OFF_AO    16600    // [2][192] own
#define OFF_FCT   16984    // 6400
#define OFF_GT    23384    // 6400
#define OFF_TOK   29784    // 256 ints
// keep large request to force 1 CTA/SM (deadlock safety)
#define SMEM_FLOATS 43504
#define SMEM_BYTES  (SMEM_FLOATS * 4)

// ============================================================================
// Fused kernel. Blocks [0,64): rnn, pair=bid/2 handles batches {2p,2p+1},
// side=bid&1 owns blocks [3s,3s+3). Blocks [64,...): decoder tiles gated by
// per-step flags. Full-smem request => 1 CTA/SM; rnn bids 0..63 are wave-1
// resident, so spinning dec CTAs can never starve them.
// ============================================================================
__global__ __launch_bounds__(1024, 1)
void fused_kernel(const int* __restrict__ input, const float* __restrict__ hidden,
                  const float* __restrict__ enc,
                  const float* __restrict__ wq,     // (6,100,128)
                  const float* __restrict__ wk,     // (2,600,128) slab 0
                  const float* __restrict__ wv,     // (2,600,128) slab 0
                  const float* __restrict__ fc_w,   // (100,128)
                  const float* __restrict__ fc_b,   // (100,)
                  const float* __restrict__ mwq,    // (6,100,64)
                  const float* __restrict__ mwk,
                  const float* __restrict__ mwv,
                  const float* __restrict__ mfc_b,
                  const float* __restrict__ mg_b,
                  const float* __restrict__ b_ih,   // (6,300)
                  const float* __restrict__ b_hh,   // (6,300)
                  const float* __restrict__ Bw,     // dec_w (10000,600)
                  const float* __restrict__ bias,   // dec_b
                  float* __restrict__ C)            // out (8192,10000)
{
    extern __shared__ float smem[];
    const int tid = threadIdx.x;

    if (blockIdx.x >= N_RNN_CTAS) {
        // ================= decoder path =================
        const int d  = blockIdx.x - N_RNN_CTAS;
        const int mt = d / N_NTILES, nt = d % N_NTILES;
        const int bm = mt * 128, bn = nt * 128;

        if (tid >= 512) return;

        if (tid == 0) {
            while (atomicAdd(&g_flag[2 * mt], 0)     < N_RNN_CTAS) __nanosleep(256);
            while (atomicAdd(&g_flag[2 * mt + 1], 0) < N_RNN_CTAS) __nanosleep(256);
            __threadfence();
        }
        asm volatile("bar.sync 1, 512;" ::: "memory");

        float* As = smem;          // [2][8][128]
        float* Bs = smem + 2048;

        const int arow = tid >> 2;
        const int kp   = (tid & 3) * 2;
        const float* Ap = g_outputs + (long)(bm + arow) * NHID + kp;
        int brow = bn + arow; if (brow > NTOKEN - 1) brow = NTOKEN - 1;
        const float* Bp = Bw + (long)brow * NHID + kp;

        const int tx = tid & 15, ty = tid >> 4;

        unsigned long long acc[4][4];
        #pragma unroll
        for (int i = 0; i < 4; i++)
            #pragma unroll
            for (int j = 0; j < 4; j++) acc[i][j] = 0ull;

        float2 ra = *(const float2*)Ap;
        float2 rb = *(const float2*)Bp;
        int buf = 0;
        As[(0 * 8 + kp) * 128 + arow]     = ra.x;
        As[(0 * 8 + kp + 1) * 128 + arow] = ra.y;
        Bs[(0 * 8 + kp) * 128 + arow]     = rb.x;
        Bs[(0 * 8 + kp + 1) * 128 + arow] = rb.y;
        asm volatile("bar.sync 1, 512;" ::: "memory");

        const int NKT = NHID / 8;
        for (int kt = 0; kt < NKT; kt++) {
            if (kt < NKT - 1) {
                ra = *(const float2*)(Ap + (kt + 1) * 8);
                rb = *(const float2*)(Bp + (kt + 1) * 8);
            }
            #pragma unroll
            for (int kk = 0; kk < 8; kk++) {
                float4 a = *(const float4*)(As + (buf * 8 + kk) * 128 + ty * 4);
                ulonglong2 b0 = *(const ulonglong2*)(Bs + (buf * 8 + kk) * 128 + tx * 8);
                ulonglong2 b1 = *(const ulonglong2*)(Bs + (buf * 8 + kk) * 128 + tx * 8 + 4);
                float av[4] = {a.x, a.y, a.z, a.w};
                unsigned long long bbv[4] = {b0.x, b0.y, b1.x, b1.y};
                #pragma unroll
                for (int i = 0; i < 4; i++) {
                    unsigned long long aa = bc2(av[i]);
                    #pragma unroll
                    for (int j = 0; j < 4; j++) ffma2(acc[i][j], aa, bbv[j]);
                }
            }
            if (kt < NKT - 1) {
                int nb = buf ^ 1;
                As[(nb * 8 + kp) * 128 + arow]     = ra.x;
                As[(nb * 8 + kp + 1) * 128 + arow] = ra.y;
                Bs[(nb * 8 + kp) * 128 + arow]     = rb.x;
                Bs[(nb * 8 + kp + 1) * 128 + arow] = rb.y;
                asm volatile("bar.sync 1, 512;" ::: "memory");
                buf = nb;
            }
        }

        const int n0 = bn + tx * 8;
        #pragma unroll
        for (int i = 0; i < 4; i++) {
            int m = bm + ty * 4 + i;
            float v[8];
            #pragma unroll
            for (int j = 0; j < 4; j++) {
                float2 p = up2(acc[i][j]);
                v[2 * j] = p.x; v[2 * j + 1] = p.y;
            }
            long base = (long)m * NTOKEN + n0;
            if (n0 + 8 <= NTOKEN) {
                #pragma unroll
                for (int j = 0; j < 8; j++) v[j] += bias[n0 + j];
                *(float4*)(C + base)     = make_float4(v[0], v[1], v[2], v[3]);
                *(float4*)(C + base + 4) = make_float4(v[4], v[5], v[6], v[7]);
            } else {
                for (int j = 0; j < 8; j++)
                    if (n0 + j < NTOKEN) C[base + j] = v[j] + bias[n0 + j];
            }
        }
        return;
    }

    // ================= rnn path =================
    const int pair = blockIdx.x >> 1;
    const int side = blockIdx.x & 1;
    const int b0   = pair * 2;
    const int nb0  = 3 * side;           // first owned global block
    const int pnb0 = 3 - nb0;            // partner's first block

    float* s_hx   = smem + OFF_HX;
    float* s_x    = smem + OFF_X;
    float* s_iu   = smem + OFF_IU;
    float* s_hn   = smem + OFF_HN;
    float* s_gx   = smem + OFF_GX;
    float* s_gh   = smem + OFF_GH;
    float* s_red  = smem + OFF_RED;
    float* s_redq = smem + OFF_REDQ;
    float* s_k0   = smem + OFF_K0;
    float* s_v0   = smem + OFF_V0;
    float* s_qp   = smem + OFF_QP;
    float* s_p    = smem + OFF_P;
    float* s_a0F  = smem + OFF_A0;
    float* s_mask = smem + OFF_MASK;
    float* s_qkvp = smem + OFF_QKVP;
    float* s_qkvF = smem + OFF_QKVF;
    float* s_aw   = smem + OFF_AW;
    float* s_ao   = smem + OFF_AO;
    float* s_fcT  = smem + OFF_FCT;
    float* s_gT   = smem + OFF_GT;
    int*   s_tok  = (int*)(smem + OFF_TOK);

    // preload: own hx blocks, fc/gate transposes, all tokens
    if (tid < 600) {
        int bb = tid / 300, r = tid % 300;
        s_hx[bb * 300 + r] = hidden[(long)(b0 + bb) * NHID + nb0 * 100 + r];
    }
    for (int j = tid; j < 6400; j += 1024) {
        s_fcT[j] = g_mhafcT[j];
        s_gT[j]  = g_gateT[j];
    }
    if (tid < 256) {
        int t = tid >> 1, bb = tid & 1;
        s_tok[tid] = input[t * BATCH + b0 + bb];
    }
    __syncthreads();

    const int w    = tid >> 5;
    const int lane = tid & 31;
    const int l4   = lane * 4;

    for (int t = 0; t < T_STEPS; t++) {
        const int par = t & 1;
        // ---- P0: embedding (full x needed by k0/v0) ----
        if (tid < 300) {
            int bb = tid / 150, j = tid % 150;
            long tok = s_tok[t * 2 + bb];
            *(float4*)(s_x + bb * 600 + j * 4) = *(const float4*)(enc + tok * NHID + j * 4);
        }
        __syncthreads();

        // ---- Phase A: k0/v0 e-half (w0-15), qp own blocks (w16-21), gh own (w22-29) ----
        if (w < 16) {
            int kv = w >> 3, ws = w & 7;
            const float* W = (kv ? wv : wk) + 64 * side + lane * 2;
            unsigned long long p0a = 0, p1a = 0;
            for (int d = ws; d < 600; d += 8) {
                unsigned long long wt = *(const unsigned long long*)(W + d * 128);
                ffma2(p0a, bc2(s_x[d]), wt);
                ffma2(p1a, bc2(s_x[600 + d]), wt);
            }
            *(float2*)(s_red + (w * 2 + 0) * 64 + lane * 2) = up2(p0a);
            *(float2*)(s_red + (w * 2 + 1) * 64 + lane * 2) = up2(p1a);
        } else if (w < 22) {
            int w2 = w - 16, nl = w2 >> 1, dp = w2 & 1;
            const float* W  = wq + ((nb0 + nl) * 100 + dp * 50) * 128 + l4;
            const float* h0 = s_hx + nl * 100 + dp * 50;
            unsigned long long a00 = 0, a01 = 0, a10 = 0, a11 = 0;
            #pragma unroll 2
            for (int d = 0; d < 50; d++) {
                ulonglong2 wt = *(const ulonglong2*)(W + d * 128);
                unsigned long long x0 = bc2(h0[d]);
                unsigned long long x1 = bc2(h0[300 + d]);
                ffma2(a00, x0, wt.x); ffma2(a01, x0, wt.y);
                ffma2(a10, x1, wt.x); ffma2(a11, x1, wt.y);
            }
            float2 p0 = up2(a00), p1 = up2(a01);
            *(float4*)(s_redq + ((w2) * 2 + 0) * 128 + l4) = make_float4(p0.x, p0.y, p1.x, p1.y);
            p0 = up2(a10); p1 = up2(a11);
            *(float4*)(s_redq + ((w2) * 2 + 1) * 128 + l4) = make_float4(p0.x, p0.y, p1.x, p1.y);
        } else if (w < 30) {
            int task = (w - 22) * 32 + lane;
            if (task < 225) {
                int kl = task / 75, g4 = (task % 75) * 4;
                const float* WT = g_gruT_hh + (nb0 + kl) * 30000 + g4;
                const float* h0 = s_hx + kl * 100;
                unsigned long long a00 = 0, a01 = 0, a10 = 0, a11 = 0;
                #pragma unroll 2
                for (int d = 0; d < 100; d += 4) {
                    float4 xa = *(const float4*)(h0 + d);
                    float4 xb = *(const float4*)(h0 + 300 + d);
                    const float* xav = (const float*)&xa;
                    const float* xbv = (const float*)&xb;
                    #pragma unroll
                    for (int c = 0; c < 4; c++) {
                        ulonglong2 wt = *(const ulonglong2*)(WT + (d + c) * 300);
                        unsigned long long x0 = bc2(xav[c]), x1 = bc2(xbv[c]);
                        ffma2(a00, x0, wt.x); ffma2(a01, x0, wt.y);
                        ffma2(a10, x1, wt.x); ffma2(a11, x1, wt.y);
                    }
                }
                float4 bi = *(const float4*)(b_hh + (nb0 + kl) * 300 + g4);
                float2 p0 = up2(a00), p1 = up2(a01);
                *(float4*)(s_gh + kl * 300 + g4) =
                    make_float4(p0.x + bi.x, p0.y + bi.y, p1.x + bi.z, p1.y + bi.w);
                p0 = up2(a10); p1 = up2(a11);
                *(float4*)(s_gh + 900 + kl * 300 + g4) =
                    make_float4(p0.x + bi.x, p0.y + bi.y, p1.x + bi.z, p1.y + bi.w);
            }
        }
        __syncthreads();

        // ---- reduce k0/v0 (publish own half) + reduce qp ----
        if (tid < 256) {
            int kv = tid >> 7, bb = (tid >> 6) & 1, e = tid & 63;
            float s = 0.f;
            #pragma unroll
            for (int ws = 0; ws < 8; ws++) s += s_red[((kv * 8 + ws) * 2 + bb) * 64 + e];
            (kv ? s_v0 : s_k0)[bb * 128 + side * 64 + e] = s;
            g_xA[par][pair][side][(kv * 2 + bb) * 64 + e] = s;
        } else if (tid < 1024) {
            int q = tid - 256;
            if (q < 768) {
                int bb = q / 384, r = q % 384, nl = r >> 7, e = r & 127;
                s_qp[bb * 384 + nl * 128 + e] =
                    s_redq[((nl * 2 + 0) * 2 + bb) * 128 + e] +
                    s_redq[((nl * 2 + 1) * 2 + bb) * 128 + e];
            }
        }
        __syncthreads();
        if (tid == 0) {
            __threadfence();
            atomicAdd(&g_sync[pair][side], 1);                    // -> 3t+1
            while (atomicAdd(&g_sync[pair][side ^ 1], 0) < 3 * t + 1) __nanosleep(64);
            __threadfence();
        }
        __syncthreads();
        if (tid < 256) {
            int kv = tid >> 7, bb = (tid >> 6) & 1, e = tid & 63;
            (kv ? s_v0 : s_k0)[bb * 128 + (side ^ 1) * 64 + e] =
                g_xA[par][pair][side ^ 1][(kv * 2 + bb) * 64 + e];
        }
        __syncthreads();

        // ---- Phase B1: p-full (w0-19, duplicated) + scores own (w20-25) ----
        if (w < 20) {
            int base = w * 10;
            #pragma unroll 2
            for (int r = 0; r < 10; r++) {
                int pr = base + r;
                int bb = pr / 100, i = pr % 100;
                float4 f = *(const float4*)(fc_w + i * 128 + l4);
                const float* vv = s_v0 + bb * 128 + l4;
                float acc = f.x * vv[0] + f.y * vv[1] + f.z * vv[2] + f.w * vv[3];
                #pragma unroll
                for (int o = 16; o > 0; o >>= 1) acc += __shfl_xor_sync(0xffffffffu, acc, o);
                if (lane == 0) s_p[bb * 104 + i] = acc;
            }
        } else if (w < 26) {
            int u = w - 20, bb = u / 3, nl = u % 3;
            const float* qv = s_qp + bb * 384 + nl * 128;
            const float* k0 = s_k0 + bb * 128;
            float acc = qv[lane] * k0[lane] + qv[lane + 32] * k0[lane + 32]
                      + qv[lane + 64] * k0[lane + 64] + qv[lane + 96] * k0[lane + 96];
            #pragma unroll
            for (int o = 16; o > 0; o >>= 1) acc += __shfl_xor_sync(0xffffffffu, acc, o);
            if (lane == 0) {
                float a = sigmoidf_(acc * 0.08838834764831845f);
                s_a0F[bb * 8 + nb0 + nl] = a;
                g_xB[par][pair][side][bb * 4 + nl] = a;
            }
        }
        __syncthreads();
        if (tid == 0) { __threadfence(); atomicAdd(&g_sync[pair][side], 1); }  // -> 3t+2
        // ---- iu own ----
        if (tid < 600) {
            int bb = tid / 300, r = tid % 300, nl = r / 100, ii = r % 100;
            s_iu[bb * 300 + r] = s_a0F[bb * 8 + nb0 + nl] * s_p[bb * 104 + ii] + fc_b[ii];
        }
        __syncthreads();

        // ---- gx own ----
        if (tid < 225) {
            int kl = tid / 75, g4 = (tid % 75) * 4;
            const float* WT = g_gruT_ih + (nb0 + kl) * 30000 + g4;
            const float* h0 = s_iu + kl * 100;
            unsigned long long a00 = 0, a01 = 0, a10 = 0, a11 = 0;
            #pragma unroll 2
            for (int d = 0; d < 100; d += 4) {
                float4 xa = *(const float4*)(h0 + d);
                float4 xb = *(const float4*)(h0 + 300 + d);
                const float* xav = (const float*)&xa;
                const float* xbv = (const float*)&xb;
                #pragma unroll
                for (int c = 0; c < 4; c++) {
                    ulonglong2 wt = *(const ulonglong2*)(WT + (d + c) * 300);
                    unsigned long long x0 = bc2(xav[c]), x1 = bc2(xbv[c]);
                    ffma2(a00, x0, wt.x); ffma2(a01, x0, wt.y);
                    ffma2(a10, x1, wt.x); ffma2(a11, x1, wt.y);
                }
            }
            float4 bi = *(const float4*)(b_ih + (nb0 + kl) * 300 + g4);
            float2 p0 = up2(a00), p1 = up2(a01);
            *(float4*)(s_gx + kl * 300 + g4) =
                make_float4(p0.x + bi.x, p0.y + bi.y, p1.x + bi.z, p1.y + bi.w);
            p0 = up2(a10); p1 = up2(a11);
            *(float4*)(s_gx + 900 + kl * 300 + g4) =
                make_float4(p0.x + bi.x, p0.y + bi.y, p1.x + bi.z, p1.y + bi.w);
        }
        __syncthreads();

        // ---- GRU elementwise own ----
        if (tid < 600) {
            int bb = tid / 300, r = tid % 300, kl = r / 100, j = r % 100;
            int gb = bb * 900 + kl * 300 + j;
            float rr = sigmoidf_(s_gx[gb]       + s_gh[gb]);
            float z  = sigmoidf_(s_gx[gb + 100] + s_gh[gb + 100]);
            float nn = tanhf(s_gx[gb + 200] + rr * s_gh[gb + 200]);
            s_hn[bb * 300 + r] = (1.f - z) * nn + z * s_hx[bb * 300 + r];
        }
        __syncthreads();

        // ---- MHA qkv own (288 tasks) ----
        if (tid < 288) {
            int mat = tid / 96, r = tid % 96, nl = r / 32, r2 = r % 32, dp = r2 / 16, e4 = (r2 % 16) * 4;
            const float* W = (mat == 0 ? mwq : (mat == 1 ? mwk : mwv))
                             + ((nb0 + nl) * 100 + dp * 50) * 64 + e4;
            const float* h0 = s_hn + nl * 100 + dp * 50;
            unsigned long long a00 = 0, a01 = 0, a10 = 0, a11 = 0;
            #pragma unroll 2
            for (int d = 0; d < 50; d += 2) {
                float2 xa = *(const float2*)(h0 + d);
                float2 xb = *(const float2*)(h0 + 300 + d);
                #pragma unroll
                for (int c = 0; c < 2; c++) {
                    ulonglong2 wt = *(const ulonglong2*)(W + (d + c) * 64);
                    unsigned long long x0 = bc2(c ? xa.y : xa.x);
                    unsigned long long x1 = bc2(c ? xb.y : xb.x);
                    ffma2(a00, x0, wt.x); ffma2(a01, x0, wt.y);
                    ffma2(a10, x1, wt.x); ffma2(a11, x1, wt.y);
                }
            }
            int o = mat * 192 + nl * 64 + e4;
            float2 p0 = up2(a00), p1 = up2(a01);
            *(float4*)(s_qkvp + (dp * 2 + 0) * 576 + o) = make_float4(p0.x, p0.y, p1.x, p1.y);
            p0 = up2(a10); p1 = up2(a11);
            *(float4*)(s_qkvp + (dp * 2 + 1) * 576 + o) = make_float4(p0.x, p0.y, p1.x, p1.y);
        }
        __syncthreads();
        // reduce dp halves, publish own, place into full array
        if (tid < 1024) {
            for (int j = tid; j < 1152; j += 1024) {
                int bb = j / 576, o = j % 576;
                float v = s_qkvp[(0 * 2 + bb) * 576 + o] + s_qkvp[(1 * 2 + bb) * 576 + o];
                int mat = o / 192, r = o % 192, nl = r / 64, e = r % 64;
                s_qkvF[bb * 1152 + mat * 384 + (nb0 + nl) * 64 + e] = v;
                g_xC[par][pair][side][bb * 576 + o] = v;
            }
        }
        __syncthreads();
        if (tid == 0) {
            __threadfence();
            atomicAdd(&g_sync[pair][side], 1);                    // -> 3t+3
            while (atomicAdd(&g_sync[pair][side ^ 1], 0) < 3 * t + 3) __nanosleep(64);
            __threadfence();
        }
        __syncthreads();
        for (int j = tid; j < 1152; j += 1024) {
            int bb = j / 576, o = j % 576;
            int mat = o / 192, r = o % 192, nl = r / 64, e = r % 64;
            s_qkvF[bb * 1152 + mat * 384 + (pnb0 + nl) * 64 + e] =
                g_xC[par][pair][side ^ 1][bb * 576 + o];
        }
        if (tid < 6) {
            int bb = tid / 3, nl = tid % 3;
            s_a0F[bb * 8 + pnb0 + nl] = g_xB[par][pair][side ^ 1][bb * 4 + nl];
        }
        __syncthreads();

        // ---- top-k mask (dup) ----
        if (tid < 2) {
            int bb = tid;
            float v[6];
            #pragma unroll
            for (int n = 0; n < 6; n++) v[n] = s_a0F[bb * 8 + n];
            #pragma unroll
            for (int a = 0; a < 6; a++)
                #pragma unroll
                for (int c = a + 1; c < 6; c++)
                    if (v[c] > v[a]) { float tmp = v[a]; v[a] = v[c]; v[c] = tmp; }
            float thr = v[3] - 0.01f;
            #pragma unroll
            for (int n = 0; n < 6; n++) s_mask[bb * 8 + n] = (s_a0F[bb * 8 + n] > thr) ? 1.f : 0.f;
        }
        // ---- attention scores (dup) ----
        if (tid < 288) {
            int bb = tid / 144, r = tid % 144, h = r / 36, i = (r % 36) / 6, j = r % 6;
            const float* qv = s_qkvF + bb * 1152 + i * 64 + h * 16;
            const float* kk = s_qkvF + bb * 1152 + 384 + j * 64 + h * 16;
            float acc = 0.f;
            #pragma unroll
            for (int d2 = 0; d2 < 16; d2++) acc += qv[d2] * kk[d2];
            s_aw[bb * 144 + h * 36 + i * 6 + j] = acc * 0.25f;
        }
        __syncthreads();
        if (tid < 48) {
            int bb = tid / 24, h = (tid % 24) / 6, i = tid % 6;
            float* row = s_aw + bb * 144 + h * 36 + i * 6;
            float m = row[0];
            #pragma unroll
            for (int j = 1; j < 6; j++) m = fmaxf(m, row[j]);
            float ex[6]; float ssum = 0.f;
            #pragma unroll
            for (int j = 0; j < 6; j++) { ex[j] = expf(row[j] - m); ssum += ex[j]; }
            float inv = 1.f / ssum;
            #pragma unroll
            for (int j = 0; j < 6; j++) row[j] = ex[j] * inv;
        }
        __syncthreads();

        // ---- attn @ V for own query blocks ----
        if (tid < 384) {
            int bb = tid / 192, r = tid % 192, nl = r / 64, e = r % 64, h = e / 16;
            const float* aw = s_aw + bb * 144 + h * 36 + (nb0 + nl) * 6;
            const float* vm = s_qkvF + bb * 1152 + 768 + e;
            float acc = 0.f;
            #pragma unroll
            for (int j = 0; j < 6; j++) acc += aw[j] * vm[j * 64];
            s_ao[bb * 192 + nl * 64 + e] = acc;
        }
        __syncthreads();

        // ---- P9: fc + gate + blend own, write output ----
        if (tid < 150) {
            int bb = tid / 75, r = tid % 75, nl = r / 25, i4 = (r % 25) * 4;
            const float* ao = s_ao + bb * 192 + nl * 64;
            unsigned long long pr0 = 0, pr1 = 0, gt0 = 0, gt1 = 0;
            #pragma unroll 4
            for (int e = 0; e < 64; e++) {
                ulonglong2 f = *(const ulonglong2*)(s_fcT + e * 100 + i4);
                ulonglong2 g = *(const ulonglong2*)(s_gT + e * 100 + i4);
                unsigned long long a2 = bc2(ao[e]);
                ffma2(pr0, a2, f.x); ffma2(pr1, a2, f.y);
                ffma2(gt0, a2, g.x); ffma2(gt1, a2, g.y);
            }
            float2 pa = up2(pr0), pb = up2(pr1), ga = up2(gt0), gb = up2(gt1);
            float prv[4] = {pa.x, pa.y, pb.x, pb.y};
            float gtv[4] = {ga.x, ga.y, gb.x, gb.y};
            float m = s_mask[bb * 8 + nb0 + nl];
            float4 o4;
            float* ov = (float*)&o4;
            #pragma unroll
            for (int c = 0; c < 4; c++) {
                int i = i4 + c;
                float pr = prv[c] + mfc_b[i];
                float gt = gtv[c] + mg_b[i];
                float hatt = sigmoidf_(gt) * tanhf(pr);
                int hidx = bb * 300 + nl * 100 + i;
                float nh = m * hatt + (1.f - m) * s_hx[hidx];
                s_hx[hidx] = nh;
                ov[c] = nh;
            }
            *(float4*)(g_outputs + ((long)t * BATCH + b0 + bb) * NHID + (nb0 + nl) * 100 + i4) = o4;
        }
        __threadfence();
        __syncthreads();
        if (tid == 0) atomicAdd(&g_flag[t], 1);
    }
}

// -------------------- tail --------------------
__global__ void tail_kernel(float* __restrict__ out, int out_size) {
    int i = blockIdx.x * blockDim.x + threadIdx.x;
    if (i < HX_ELEMS && (long)out_size >= DEC_ELEMS + HX_ELEMS)
        out[DEC_ELEMS + i] = g_outputs[(long)(T_STEPS - 1) * HX_ELEMS + i];
    if (i == 0 && (long)out_size >= DEC_ELEMS + HX_ELEMS + 1)
        out[DEC_ELEMS + HX_ELEMS] = 0.0f;
}

extern "C" void kernel_launch(void* const* d_in, const int* in_sizes, int n_in,
                              void* d_out, int out_size) {
    const int*   input      = (const int*)  d_in[0];
    const float* hidden     = (const float*)d_in[1];
    const float* encoder_w  = (const float*)d_in[2];
    const float* inp_wq     = (const float*)d_in[3];
    const float* inp_wk     = (const float*)d_in[4];
    const float* inp_wv     = (const float*)d_in[5];
    const float* inp_fc_w   = (const float*)d_in[6];
    const float* inp_fc_b   = (const float*)d_in[7];
    const float* mha_wq     = (const float*)d_in[8];
    const float* mha_wk     = (const float*)d_in[9];
    const float* mha_wv     = (const float*)d_in[10];
    const float* mha_fc_w   = (const float*)d_in[11];
    const float* mha_fc_b   = (const float*)d_in[12];
    const float* mha_gate_w = (const float*)d_in[13];
    const float* mha_gate_b = (const float*)d_in[14];
    const float* gru_w_ih   = (const float*)d_in[15];
    const float* gru_w_hh   = (const float*)d_in[16];
    const float* gru_b_ih   = (const float*)d_in[17];
    const float* gru_b_hh   = (const float*)d_in[18];
    const float* dec_w      = (const float*)d_in[19];
    const float* dec_b      = (const float*)d_in[20];
    float* out = (float*)d_out;

    cudaFuncSetAttribute(fused_kernel, cudaFuncAttributeMaxDynamicSharedMemorySize, SMEM_BYTES);

    prep_kernel<<<704, 256>>>(gru_w_ih, gru_w_hh, mha_fc_w, mha_gate_w);

    const int grid = N_RNN_CTAS + N_MTILES * N_NTILES;   // 64 + 5056
    fused_kernel<<<grid, 1024, SMEM_BYTES>>>(input, hidden, encoder_w,
                                inp_wq, inp_wk, inp_wv, inp_fc_w, inp_fc_b,
                                mha_wq, mha_wk, mha_wv, mha_fc_b, mha_gate_b,
                                gru_b_ih, gru_b_hh,
                                dec_w, dec_b, out);

    tail_kernel<<<(HX_ELEMS + 255) / 256, 256>>>(out, out_size);
}

// round 16
// speedup vs baseline: 1.1477x; 1.1477x over previous
#include <cuda_runtime.h>
#include <cuda_bf16.h>
#include <math.h>

// Problem constants
#define T_STEPS 128
#define BATCH   64
#define NTOKEN  10000
#define NB      6
#define BS      100
#define NHID    600
#define EMHA    64
#define DEC_ELEMS 81920000L
#define HX_ELEMS  38400

#define N_RNN_CTAS 32
#define N_NTILES   79
#define N_MTILES   64
#define N_DEC_TOTAL (N_MTILES * N_NTILES)   // 5056
#define N_PREP_CTAS 8

// -------------------- device scratch (no allocations allowed) --------------------
__device__ float g_outputs[T_STEPS * BATCH * NHID];
__device__ float g_gruT_ih[NB * BS * 3 * BS];         // [k][d][g]
__device__ float g_gruT_hh[NB * BS * 3 * BS];
__device__ float g_mhafcT[EMHA * BS];                 // [e][i]
__device__ float g_gateT[EMHA * BS];
__device__ int   g_flag[T_STEPS];                     // per-step rnn completion (0..32)
__device__ int   g_prep_done;                         // 0..8
__device__ int   g_dec_done;                          // 0..5056

// -------------------- helpers --------------------
__device__ __forceinline__ float sigmoidf_(float x) { return 1.f / (1.f + expf(-x)); }
__device__ __forceinline__ void ffma2(unsigned long long& a, unsigned long long x, unsigned long long y) {
    asm("fma.rn.f32x2 %0, %1, %2, %0;" : "+l"(a) : "l"(x), "l"(y));
}
__device__ __forceinline__ unsigned long long bc2(float x) {
    unsigned long long r;
    asm("mov.b64 %0, {%1, %1};" : "=l"(r) : "r"(__float_as_uint(x)));
    return r;
}
__device__ __forceinline__ float2 up2(unsigned long long a) {
    unsigned lo, hi;
    asm("mov.b64 {%0, %1}, %2;" : "=r"(lo), "=r"(hi) : "l"(a));
    return make_float2(__uint_as_float(lo), __uint_as_float(hi));
}

// -------------------- rnn smem layout (floats) --------------------
#define OFF_HX    0        // [2][600]
#define OFF_X     1200     // [2 buf][2 b][600]  double-buffered embedding
#define OFF_IU    3600     // [2][600]
#define OFF_HN    4800     // [2][600]
#define OFF_GX    6000     // [2][1800]
#define OFF_GH    9600     // [2][1800]
#define OFF_RED   13200    // 8192
#define OFF_QKVP  21392    // [2dp][2b][1152]
#define OFF_QKV   26000    // [2][1152]
#define OFF_K0    28304    // [2][128]
#define OFF_V0    28560    // [2][128]
#define OFF_QP    28816    // [2][768]
#define OFF_P     30352    // [2][104]
#define OFF_A0    30560    // [2][8]
#define OFF_MASK  30576    // [2][8]
#define OFF_AW    30592    // [2][144]
#define OFF_AO    30880    // [2][384]
#define OFF_FCT   31648    // 6400
#define OFF_GT    38048    // 6400
#define OFF_TOK   44448    // 256 ints
#define SMEM_FLOATS 44704
#define SMEM_BYTES  (SMEM_FLOATS * 4)   // 178816 B -> 1 CTA/SM guaranteed

// ============================================================================
// Single fused kernel.
//   blocks [0,32):        rnn, 2 batch elements each (wait for prep counter)
//   blocks [32,32+5056):  decoder tiles gated by per-step flags; first 8 dec
//                         CTAs (wave-1 resident) do the weight transposes.
// Every CTA requests 174+KB dynamic smem => 1 CTA/SM; rnn + prep CTAs are
// wave-1 resident, so spinning CTAs can never starve them (deadlock-free).
// The LAST dec CTA to finish resets all flags -> kernel is replay-safe.
// ============================================================================
__global__ __launch_bounds__(1024, 1)
void fused_kernel(const int* __restrict__ input, const float* __restrict__ hidden,
                  const float* __restrict__ enc,
                  const float* __restrict__ wq,     // (6,100,128)
                  const float* __restrict__ wk,     // (2,600,128) slab 0
                  const float* __restrict__ wv,     // (2,600,128) slab 0
                  const float* __restrict__ fc_w,   // (100,128)
                  const float* __restrict__ fc_b,   // (100,)
                  const float* __restrict__ mwq,    // (6,100,64)
                  const float* __restrict__ mwk,
                  const float* __restrict__ mwv,
                  const float* __restrict__ mfc_b,
                  const float* __restrict__ mg_b,
                  const float* __restrict__ b_ih,   // (6,300)
                  const float* __restrict__ b_hh,   // (6,300)
                  const float* __restrict__ gru_w_ih, // raw (6,300,100)
                  const float* __restrict__ gru_w_hh,
                  const float* __restrict__ mfc_raw,  // (100,64)
                  const float* __restrict__ mgate_raw,
                  const float* __restrict__ Bw,     // dec_w (10000,600)
                  const float* __restrict__ bias,   // dec_b
                  float* __restrict__ C,            // out
                  int out_size)
{
    extern __shared__ float smem[];
    const int tid = threadIdx.x;

    if (blockIdx.x >= N_RNN_CTAS) {
        // ================= decoder path =================
        const int d  = blockIdx.x - N_RNN_CTAS;

        // --- first 8 dec CTAs (wave-1 resident) do the one-time transposes ---
        if (d < N_PREP_CTAS) {
            const int CH = (NB * 3 * BS * BS) / N_PREP_CTAS;   // 22500
            for (int i = d * CH + tid; i < (d + 1) * CH; i += 1024) {
                int k = i / (3 * BS * BS);
                int r = i % (3 * BS * BS);
                int g = r / BS;
                int dd = r % BS;
                int dst = k * (BS * 3 * BS) + dd * (3 * BS) + g;
                g_gruT_ih[dst] = gru_w_ih[i];
                g_gruT_hh[dst] = gru_w_hh[i];
            }
            if (d == 0) {
                for (int i = tid; i < BS * EMHA; i += 1024) {
                    int r = i / EMHA, e = i % EMHA;
                    g_mhafcT[e * BS + r] = mfc_raw[i];
                    g_gateT[e * BS + r]  = mgate_raw[i];
                }
            }
            __syncthreads();
            if (tid == 0) { __threadfence(); atomicAdd(&g_prep_done, 1); }
        }

        if (tid >= 512) return;

        const int mt = d / N_NTILES, nt = d % N_NTILES;
        const int bm = mt * 128, bn = nt * 128;

        if (tid == 0) {
            while (atomicAdd(&g_flag[2 * mt], 0)     < N_RNN_CTAS) __nanosleep(256);
            while (atomicAdd(&g_flag[2 * mt + 1], 0) < N_RNN_CTAS) __nanosleep(256);
            __threadfence();
        }
        asm volatile("bar.sync 1, 512;" ::: "memory");

        float* As = smem;          // [2][8][128]
        float* Bs = smem + 2048;

        const int arow = tid >> 2;
        const int kp   = (tid & 3) * 2;
        const float* Ap = g_outputs + (long)(bm + arow) * NHID + kp;
        int brow = bn + arow; if (brow > NTOKEN - 1) brow = NTOKEN - 1;
        const float* Bp = Bw + (long)brow * NHID + kp;

        const int tx = tid & 15, ty = tid >> 4;

        unsigned long long acc[4][4];
        #pragma unroll
        for (int i = 0; i < 4; i++)
            #pragma unroll
            for (int j = 0; j < 4; j++) acc[i][j] = 0ull;

        float2 ra = *(const float2*)Ap;
        float2 rb = *(const float2*)Bp;
        int buf = 0;
        As[(0 * 8 + kp) * 128 + arow]     = ra.x;
        As[(0 * 8 + kp + 1) * 128 + arow] = ra.y;
        Bs[(0 * 8 + kp) * 128 + arow]     = rb.x;
        Bs[(0 * 8 + kp + 1) * 128 + arow] = rb.y;
        asm volatile("bar.sync 1, 512;" ::: "memory");

        const int NKT = NHID / 8;
        for (int kt = 0; kt < NKT; kt++) {
            if (kt < NKT - 1) {
                ra = *(const float2*)(Ap + (kt + 1) * 8);
                rb = *(const float2*)(Bp + (kt + 1) * 8);
            }
            #pragma unroll
            for (int kk = 0; kk < 8; kk++) {
                float4 a = *(const float4*)(As + (buf * 8 + kk) * 128 + ty * 4);
                ulonglong2 b0 = *(const ulonglong2*)(Bs + (buf * 8 + kk) * 128 + tx * 8);
                ulonglong2 b1 = *(const ulonglong2*)(Bs + (buf * 8 + kk) * 128 + tx * 8 + 4);
                float av[4] = {a.x, a.y, a.z, a.w};
                unsigned long long bbv[4] = {b0.x, b0.y, b1.x, b1.y};
                #pragma unroll
                for (int i = 0; i < 4; i++) {
                    unsigned long long aa = bc2(av[i]);
                    #pragma unroll
                    for (int j = 0; j < 4; j++) ffma2(acc[i][j], aa, bbv[j]);
                }
            }
            if (kt < NKT - 1) {
                int nb = buf ^ 1;
                As[(nb * 8 + kp) * 128 + arow]     = ra.x;
                As[(nb * 8 + kp + 1) * 128 + arow] = ra.y;
                Bs[(nb * 8 + kp) * 128 + arow]     = rb.x;
                Bs[(nb * 8 + kp + 1) * 128 + arow] = rb.y;
                asm volatile("bar.sync 1, 512;" ::: "memory");
                buf = nb;
            }
        }

        const int n0 = bn + tx * 8;
        #pragma unroll
        for (int i = 0; i < 4; i++) {
            int m = bm + ty * 4 + i;
            float v[8];
            #pragma unroll
            for (int j = 0; j < 4; j++) {
                float2 p = up2(acc[i][j]);
                v[2 * j] = p.x; v[2 * j + 1] = p.y;
            }
            long base = (long)m * NTOKEN + n0;
            if (n0 + 8 <= NTOKEN) {
                #pragma unroll
                for (int j = 0; j < 8; j++) v[j] += bias[n0 + j];
                *(float4*)(C + base)     = make_float4(v[0], v[1], v[2], v[3]);
                *(float4*)(C + base + 4) = make_float4(v[4], v[5], v[6], v[7]);
            } else {
                for (int j = 0; j < 8; j++)
                    if (n0 + j < NTOKEN) C[base + j] = v[j] + bias[n0 + j];
            }
        }

        // --- last dec CTA resets flags for the next graph replay ---
        asm volatile("bar.sync 1, 512;" ::: "memory");
        if (tid == 0) {
            __threadfence();
            int old = atomicAdd(&g_dec_done, 1);
            if (old == N_DEC_TOTAL - 1) {
                for (int i = 0; i < T_STEPS; i++) g_flag[i] = 0;
                g_prep_done = 0;
                g_dec_done  = 0;
                __threadfence();
            }
        }
        return;
    }

    // ================= rnn path =================
    const int b0 = blockIdx.x * 2;

    float* s_hx   = smem + OFF_HX;
    float* s_xb   = smem + OFF_X;       // [2][1200]
    float* s_iu   = smem + OFF_IU;
    float* s_hn   = smem + OFF_HN;
    float* s_gx   = smem + OFF_GX;
    float* s_gh   = smem + OFF_GH;
    float* s_red  = smem + OFF_RED;
    float* s_qkvp = smem + OFF_QKVP;
    float* s_qkv  = smem + OFF_QKV;
    float* s_k0   = smem + OFF_K0;
    float* s_v0   = smem + OFF_V0;
    float* s_qp   = smem + OFF_QP;
    float* s_p    = smem + OFF_P;
    float* s_a0   = smem + OFF_A0;
    float* s_mask = smem + OFF_MASK;
    float* s_aw   = smem + OFF_AW;
    float* s_ao   = smem + OFF_AO;
    float* s_fcT  = smem + OFF_FCT;
    float* s_gT   = smem + OFF_GT;
    int*   s_tok  = (int*)(smem + OFF_TOK);

    // wait for prep CTAs (transposed weights) before touching them
    if (tid == 0) {
        while (atomicAdd(&g_prep_done, 0) < N_PREP_CTAS) __nanosleep(128);
        __threadfence();
    }
    __syncthreads();

    // preload: hx, cached fc/gate transposes, all tokens, x for t=0
    for (int j = tid; j < 1200; j += 1024)
        s_hx[j] = hidden[(long)(b0 + j / 600) * NHID + (j % 600)];
    for (int j = tid; j < 6400; j += 1024) {
        s_fcT[j] = g_mhafcT[j];
        s_gT[j]  = g_gateT[j];
    }
    if (tid < 256) {
        int t = tid >> 1, bb = tid & 1;
        s_tok[tid] = input[t * BATCH + b0 + bb];
    }
    __syncthreads();
    if (tid < 300) {
        int bb = tid / 150, j = tid % 150;
        long tok = s_tok[bb];
        *(float4*)(s_xb + bb * 600 + j * 4) = *(const float4*)(enc + tok * NHID + j * 4);
    }
    __syncthreads();

    const int w    = tid >> 5;
    const int lane = tid & 31;
    const int l4   = lane * 4;

    for (int t = 0; t < T_STEPS; t++) {
        const float* s_x = s_xb + (t & 1) * 1200;

        // ---- Phase A: k0/v0 partials (warps 0-19) + q_proj partials (warps 20-31) ----
        if (w < 20) {
            int kv = w / 10, ws = w % 10;
            const float* W = kv ? wv : wk;   // slab 0
            unsigned long long a00 = 0, a01 = 0, a10 = 0, a11 = 0;
            for (int d = ws; d < 600; d += 10) {
                ulonglong2 wt = *(const ulonglong2*)(W + d * 128 + l4);
                unsigned long long x0 = bc2(s_x[d]);
                unsigned long long x1 = bc2(s_x[600 + d]);
                ffma2(a00, x0, wt.x); ffma2(a01, x0, wt.y);
                ffma2(a10, x1, wt.x); ffma2(a11, x1, wt.y);
            }
            float2 p0 = up2(a00), p1 = up2(a01);
            *(float4*)(s_red + ((kv * 10 + ws) * 2 + 0) * 128 + l4) = make_float4(p0.x, p0.y, p1.x, p1.y);
            p0 = up2(a10); p1 = up2(a11);
            *(float4*)(s_red + ((kv * 10 + ws) * 2 + 1) * 128 + l4) = make_float4(p0.x, p0.y, p1.x, p1.y);
        } else {
            int u = w - 20, n = u >> 1, dp = u & 1;
            const float* W  = wq + (n * 100 + dp * 50) * 128;
            const float* h0 = s_hx + n * 100 + dp * 50;
            unsigned long long a00 = 0, a01 = 0, a10 = 0, a11 = 0;
            #pragma unroll 2
            for (int d = 0; d < 50; d++) {
                ulonglong2 wt = *(const ulonglong2*)(W + d * 128 + l4);
                unsigned long long x0 = bc2(h0[d]);
                unsigned long long x1 = bc2(h0[600 + d]);
                ffma2(a00, x0, wt.x); ffma2(a01, x0, wt.y);
                ffma2(a10, x1, wt.x); ffma2(a11, x1, wt.y);
            }
            float2 p0 = up2(a00), p1 = up2(a01);
            *(float4*)(s_red + 5120 + ((n * 2 + dp) * 2 + 0) * 128 + l4) = make_float4(p0.x, p0.y, p1.x, p1.y);
            p0 = up2(a10); p1 = up2(a11);
            *(float4*)(s_red + 5120 + ((n * 2 + dp) * 2 + 1) * 128 + l4) = make_float4(p0.x, p0.y, p1.x, p1.y);
        }
        __syncthreads();

        // ---- Reduce: k0/v0 (sum 10) and qp (sum 2) ----
        for (int j = tid; j < 2048; j += 1024) {
            if (j < 512) {
                int kv = j >> 8, bb = (j >> 7) & 1, e = j & 127;
                float s = 0.f;
                #pragma unroll
                for (int ws = 0; ws < 10; ws++) s += s_red[((kv * 10 + ws) * 2 + bb) * 128 + e];
                (kv ? s_v0 : s_k0)[bb * 128 + e] = s;
            } else {
                int q = j - 512;
                int n = q >> 8, bb = (q >> 7) & 1, e = q & 127;
                s_qp[bb * 768 + n * 128 + e] =
                    s_red[5120 + ((n * 2 + 0) * 2 + bb) * 128 + e] +
                    s_red[5120 + ((n * 2 + 1) * 2 + bb) * 128 + e];
            }
        }
        __syncthreads();

        // ---- P2: scores (warps 0-11) + p = v0 @ fc^T (warps 12-31) ----
        if (w < 12) {
            int bb = w / 6, n = w % 6;
            const float* qv = s_qp + bb * 768 + n * 128;
            const float* k0 = s_k0 + bb * 128;
            float acc = qv[lane] * k0[lane] + qv[lane + 32] * k0[lane + 32]
                      + qv[lane + 64] * k0[lane + 64] + qv[lane + 96] * k0[lane + 96];
            #pragma unroll
            for (int o = 16; o > 0; o >>= 1) acc += __shfl_xor_sync(0xffffffffu, acc, o);
            if (lane == 0) s_a0[bb * 8 + n] = sigmoidf_(acc * 0.08838834764831845f);
        } else {
            int base = (w - 12) * 10;
            #pragma unroll 2
            for (int r = 0; r < 10; r++) {
                int pair = base + r;
                int bb = pair / 100, i = pair % 100;
                float4 f = *(const float4*)(fc_w + i * 128 + l4);
                const float* vv = s_v0 + bb * 128 + l4;
                float acc = f.x * vv[0] + f.y * vv[1] + f.z * vv[2] + f.w * vv[3];
                #pragma unroll
                for (int o = 16; o > 0; o >>= 1) acc += __shfl_xor_sync(0xffffffffu, acc, o);
                if (lane == 0) s_p[bb * 104 + i] = acc;
            }
        }
        __syncthreads();

        // ---- P2b: top-k mask + inp_use ----
        if (tid < 2) {
            int bb = tid;
            float v[6];
            #pragma unroll
            for (int n = 0; n < 6; n++) v[n] = s_a0[bb * 8 + n];
            #pragma unroll
            for (int a = 0; a < 6; a++)
                #pragma unroll
                for (int c = a + 1; c < 6; c++)
                    if (v[c] > v[a]) { float tmp = v[a]; v[a] = v[c]; v[c] = tmp; }
            float thr = v[3] - 0.01f;
            #pragma unroll
            for (int n = 0; n < 6; n++) s_mask[bb * 8 + n] = (s_a0[bb * 8 + n] > thr) ? 1.f : 0.f;
        }
        for (int j = tid; j < 1200; j += 1024) {
            int bb = j / 600, i = j % 600, n = i / 100, ii = i % 100;
            s_iu[bb * 600 + i] = s_a0[bb * 8 + n] * s_p[bb * 104 + ii] + fc_b[ii];
        }
        __syncthreads();

        // ---- P4: GRU gate matvecs ----
        if (tid < 900) {
            int h = tid / 450, r = tid % 450, k = r / 75, g = (r % 75) * 4;
            const float* WT = (h ? g_gruT_hh : g_gruT_ih) + k * 30000 + g;
            const float* s0 = (h ? s_hx : s_iu) + k * 100;
            const float* bias2 = (h ? b_hh : b_ih) + k * 300 + g;
            unsigned long long a00 = 0, a01 = 0, a10 = 0, a11 = 0;
            #pragma unroll 4
            for (int d = 0; d < 100; d++) {
                ulonglong2 wt = *(const ulonglong2*)(WT + d * 300);
                unsigned long long x0 = bc2(s0[d]);
                unsigned long long x1 = bc2(s0[600 + d]);
                ffma2(a00, x0, wt.x); ffma2(a01, x0, wt.y);
                ffma2(a10, x1, wt.x); ffma2(a11, x1, wt.y);
            }
            float4 bi = *(const float4*)bias2;
            float* dst = h ? s_gh : s_gx;
            float2 p0 = up2(a00), p1 = up2(a01);
            *(float4*)(dst + k * 300 + g) =
                make_float4(p0.x + bi.x, p0.y + bi.y, p1.x + bi.z, p1.y + bi.w);
            p0 = up2(a10); p1 = up2(a11);
            *(float4*)(dst + 1800 + k * 300 + g) =
                make_float4(p0.x + bi.x, p0.y + bi.y, p1.x + bi.z, p1.y + bi.w);
        }
        __syncthreads();

        // ---- P5: GRU elementwise ----
        for (int j = tid; j < 1200; j += 1024) {
            int bb = j / 600, i = j % 600, k = i / 100, jj = i % 100;
            int base = bb * 1800 + k * 300 + jj;
            float r  = sigmoidf_(s_gx[base]       + s_gh[base]);
            float z  = sigmoidf_(s_gx[base + 100] + s_gh[base + 100]);
            float nn = tanhf(s_gx[base + 200] + r * s_gh[base + 200]);
            s_hn[bb * 600 + i] = (1.f - z) * nn + z * s_hx[bb * 600 + i];
        }
        __syncthreads();

        // ---- P6: MHA q/k/v projections + prefetch x for t+1 ----
        if (tid < 576) {
            int part = tid / 288, r = tid % 288;
            int which = r / 96, n = (r % 96) / 16, e4 = (r % 16) * 4;
            const float* W = (which == 0 ? mwq : (which == 1 ? mwk : mwv))
                             + (n * 100 + part * 50) * 64 + e4;
            const float* h0 = s_hn + n * 100 + part * 50;
            unsigned long long a00 = 0, a01 = 0, a10 = 0, a11 = 0;
            #pragma unroll 2
            for (int d = 0; d < 50; d++) {
                ulonglong2 wt = *(const ulonglong2*)(W + d * 64);
                unsigned long long x0 = bc2(h0[d]);
                unsigned long long x1 = bc2(h0[600 + d]);
                ffma2(a00, x0, wt.x); ffma2(a01, x0, wt.y);
                ffma2(a10, x1, wt.x); ffma2(a11, x1, wt.y);
            }
            int o = which * 384 + n * 64 + e4;
            float2 p0 = up2(a00), p1 = up2(a01);
            *(float4*)(s_qkvp + (part * 2 + 0) * 1152 + o) = make_float4(p0.x, p0.y, p1.x, p1.y);
            p0 = up2(a10); p1 = up2(a11);
            *(float4*)(s_qkvp + (part * 2 + 1) * 1152 + o) = make_float4(p0.x, p0.y, p1.x, p1.y);
        } else if (tid < 876 && t + 1 < T_STEPS) {
            int u = tid - 576;                 // 0..299
            int bb = u / 150, j = u % 150;
            long tok = s_tok[(t + 1) * 2 + bb];
            *(float4*)(s_xb + ((t + 1) & 1) * 1200 + bb * 600 + j * 4) =
                *(const float4*)(enc + tok * NHID + j * 4);
        }
        __syncthreads();
        for (int j = tid; j < 2304; j += 1024) {
            int bb = j / 1152, o = j % 1152;
            s_qkv[bb * 1152 + o] = s_qkvp[(0 * 2 + bb) * 1152 + o] + s_qkvp[(1 * 2 + bb) * 1152 + o];
        }
        __syncthreads();

        // ---- P7: attention scores + softmax ----
        if (tid < 288) {
            int bb = tid / 144, r = tid % 144, h = r / 36, i = (r % 36) / 6, j = r % 6;
            const float* qv = s_qkv + bb * 1152 + i * 64 + h * 16;
            const float* kk = s_qkv + bb * 1152 + 384 + j * 64 + h * 16;
            float acc = 0.f;
            #pragma unroll
            for (int d2 = 0; d2 < 16; d2++) acc += qv[d2] * kk[d2];
            s_aw[bb * 144 + h * 36 + i * 6 + j] = acc * 0.25f;
        }
        __syncthreads();
        if (tid < 48) {
            int bb = tid / 24, h = (tid % 24) / 6, i = tid % 6;
            float* row = s_aw + bb * 144 + h * 36 + i * 6;
            float m = row[0];
            #pragma unroll
            for (int j = 1; j < 6; j++) m = fmaxf(m, row[j]);
            float ex[6]; float ssum = 0.f;
            #pragma unroll
            for (int j = 0; j < 6; j++) { ex[j] = expf(row[j] - m); ssum += ex[j]; }
            float inv = 1.f / ssum;
            #pragma unroll
            for (int j = 0; j < 6; j++) row[j] = ex[j] * inv;
        }
        __syncthreads();

        // ---- P8: attn @ V ----
        if (tid < 768) {
            int bb = tid / 384, r = tid % 384, n = r / 64, e = r % 64, h = e / 16;
            const float* aw = s_aw + bb * 144 + h * 36 + n * 6;
            const float* vm = s_qkv + bb * 1152 + 768 + e;
            float acc = 0.f;
            #pragma unroll
            for (int j = 0; j < 6; j++) acc += aw[j] * vm[j * 64];
            s_ao[bb * 384 + r] = acc;
        }
        __syncthreads();

        // ---- P9: fc proj + gate + masked blend, write output ----
        if (tid < 300) {
            int bb = tid / 150, r = tid % 150, n = r / 25, i4 = (r % 25) * 4;
            const float* ao = s_ao + bb * 384 + n * 64;
            unsigned long long pr0 = 0, pr1 = 0, gt0 = 0, gt1 = 0;
            #pragma unroll 4
            for (int e = 0; e < 64; e++) {
                ulonglong2 f = *(const ulonglong2*)(s_fcT + e * 100 + i4);
                ulonglong2 g = *(const ulonglong2*)(s_gT + e * 100 + i4);
                unsigned long long a2 = bc2(ao[e]);
                ffma2(pr0, a2, f.x); ffma2(pr1, a2, f.y);
                ffma2(gt0, a2, g.x); ffma2(gt1, a2, g.y);
            }
            float2 pa = up2(pr0), pb = up2(pr1), ga = up2(gt0), gb = up2(gt1);
            float prv[4] = {pa.x, pa.y, pb.x, pb.y};
            float gtv[4] = {ga.x, ga.y, gb.x, gb.y};
            float m = s_mask[bb * 8 + n];
            float4 o4;
            float* ov = (float*)&o4;
            #pragma unroll
            for (int c = 0; c < 4; c++) {
                int i = i4 + c;
                float pr = prv[c] + mfc_b[i];
                float gt = gtv[c] + mg_b[i];
                float hatt = sigmoidf_(gt) * tanhf(pr);
                int hidx = bb * 600 + n * 100 + i;
                float nh = m * hatt + (1.f - m) * s_hx[hidx];
                s_hx[hidx] = nh;
                ov[c] = nh;
            }
            long obase = ((long)t * BATCH + b0 + bb) * NHID + n * 100 + i4;
            *(float4*)(g_outputs + obase) = o4;
            // folded tail: hx_final region of d_out (only if harness expects it)
            if (t == T_STEPS - 1 && (long)out_size >= DEC_ELEMS + HX_ELEMS)
                *(float4*)(C + DEC_ELEMS + (long)(b0 + bb) * NHID + n * 100 + i4) = o4;
        }
        __threadfence();
        __syncthreads();
        if (tid == 0) atomicAdd(&g_flag[t], 1);
    }

    if (blockIdx.x == 0 && tid == 0 && (long)out_size >= DEC_ELEMS + HX_ELEMS + 1)
        C[DEC_ELEMS + HX_ELEMS] = 0.0f;
}

extern "C" void kernel_launch(void* const* d_in, const int* in_sizes, int n_in,
                              void* d_out, int out_size) {
    const int*   input      = (const int*)  d_in[0];
    const float* hidden     = (const float*)d_in[1];
    const float* encoder_w  = (const float*)d_in[2];
    const float* inp_wq     = (const float*)d_in[3];
    const float* inp_wk     = (const float*)d_in[4];
    const float* inp_wv     = (const float*)d_in[5];
    const float* inp_fc_w   = (const float*)d_in[6];
    const float* inp_fc_b   = (const float*)d_in[7];
    const float* mha_wq     = (const float*)d_in[8];
    const float* mha_wk     = (const float*)d_in[9];
    const float* mha_wv     = (const float*)d_in[10];
    const float* mha_fc_w   = (const float*)d_in[11];
    const float* mha_fc_b   = (const float*)d_in[12];
    const float* mha_gate_w = (const float*)d_in[13];
    const float* mha_gate_b = (const float*)d_in[14];
    const float* gru_w_ih   = (const float*)d_in[15];
    const float* gru_w_hh   = (const float*)d_in[16];
    const float* gru_b_ih   = (const float*)d_in[17];
    const float* gru_b_hh   = (const float*)d_in[18];
    const float* dec_w      = (const float*)d_in[19];
    const float* dec_b      = (const float*)d_in[20];
    float* out = (float*)d_out;

    cudaFuncSetAttribute(fused_kernel, cudaFuncAttributeMaxDynamicSharedMemorySize, SMEM_BYTES);

    const int grid = N_RNN_CTAS + N_DEC_TOTAL;   // 32 + 5056
    fused_kernel<<<grid, 1024, SMEM_BYTES>>>(input, hidden, encoder_w,
                                inp_wq, inp_wk, inp_wv, inp_fc_w, inp_fc_b,
                                mha_wq, mha_wk, mha_wv, mha_fc_b, mha_gate_b,
                                gru_b_ih, gru_b_hh,
                                gru_w_ih, gru_w_hh, mha_fc_w, mha_gate_w,
                                dec_w, dec_b, out, out_size);
}